// round 6
// baseline (speedup 1.0000x reference)
#include <cuda_runtime.h>

#define Bn 4096
#define Sn 64
#define Un 128
#define Mn 32
#define NUNF 6
#define EPSF 1e-8f
#define NWARP 7
#define NTHR (NWARP*32)

typedef unsigned long long u64;

__device__ __forceinline__ float ftanh(float x) {
    float t; asm("tanh.approx.f32 %0, %1;" : "=f"(t) : "f"(x));
    return t;
}
__device__ __forceinline__ u64 pk2(float lo, float hi) {
    u64 p; asm("mov.b64 %0, {%1,%2};" : "=l"(p) : "f"(lo), "f"(hi)); return p;
}
__device__ __forceinline__ float lo2(u64 p) {
    float a, b; asm("mov.b64 {%0,%1}, %2;" : "=f"(a), "=f"(b) : "l"(p)); return a;
}
__device__ __forceinline__ float hi2(u64 p) {
    float a, b; asm("mov.b64 {%0,%1}, %2;" : "=f"(a), "=f"(b) : "l"(p)); return b;
}
__device__ __forceinline__ u64 fma2(u64 a, u64 b, u64 c) {
    u64 d; asm("fma.rn.f32x2 %0, %1, %2, %3;" : "=l"(d) : "l"(a), "l"(b), "l"(c)); return d;
}

// Single fused kernel. 148 CTAs x 224 threads (7 warps), 4 batches per warp.
__global__ __launch_bounds__(NTHR, 1) void ltc_all(
    const float* __restrict__ inputs, const float* __restrict__ state,
    const float* __restrict__ gleak,  const float* __restrict__ vleak,
    const float* __restrict__ cm,
    const float* __restrict__ sigma,  const float* __restrict__ mu,
    const float* __restrict__ w,      const float* __restrict__ erev,
    const float* __restrict__ ssig,   const float* __restrict__ smu,
    const float* __restrict__ sw,     const float* __restrict__ serev,
    const float* __restrict__ mask,   const float* __restrict__ smask,
    const float* __restrict__ inw,    const float* __restrict__ inb,
    const float* __restrict__ outw,   const float* __restrict__ outb,
    float* __restrict__ dout)
{
    extern __shared__ float sm[];
    float* sAf = sm;                       // Un*Un  a = 0.5*sigma
    float* sBf = sm + Un*Un;               // Un*Un  b = -0.5*sigma*mu
    float* sWf = sm + 2*Un*Un;             // Un*Un  we = 0.5*w*mask*erev
    float* sV  = sm + 3*Un*Un;             // NWARP * 512 floats (x staging / v pairs)
    float* sSCn= sV + NWARP*4*Un;          // Un sensory col num-sums
    float* sSCd= sSCn + Un;
    float* sNB = sSCd + Un;                // Un nbase
    float* sDB = sNB + Un;                 // Un dbase

    int tid = threadIdx.x;

    // ---- A1: fold sensory params into SMEM (first 32KB of each region) ----
    {
        const float4* s4 = (const float4*)ssig;
        const float4* m4 = (const float4*)smu;
        const float4* w4 = (const float4*)sw;
        const float4* e4 = (const float4*)serev;
        const float4* k4 = (const float4*)smask;
        for (int i = tid; i < Sn*Un/4; i += NTHR) {
            float4 sg = s4[i], mm = m4[i], ww = w4[i], ee = e4[i], kk = k4[i];
            float4 a, b, we;
            a.x = 0.5f*sg.x; a.y = 0.5f*sg.y; a.z = 0.5f*sg.z; a.w = 0.5f*sg.w;
            b.x = -a.x*mm.x; b.y = -a.y*mm.y; b.z = -a.z*mm.z; b.w = -a.w*mm.w;
            we.x = 0.5f*ww.x*kk.x*ee.x; we.y = 0.5f*ww.y*kk.y*ee.y;
            we.z = 0.5f*ww.z*kk.z*ee.z; we.w = 0.5f*ww.w*kk.w*ee.w;
            ((float4*)sAf)[i] = a; ((float4*)sBf)[i] = b; ((float4*)sWf)[i] = we;
        }
    }
    __syncthreads();

    int warp = tid >> 5, lane = tid & 31, d0 = lane * 4;
    int start = (int)(((long long)blockIdx.x       * Bn) / gridDim.x);
    int end   = (int)(((long long)(blockIdx.x + 1) * Bn) / gridDim.x);
    int b0 = start + warp*4;
    int b1 = (b0+1 < end) ? b0+1 : end-1;
    int b2 = (b0+2 < end) ? b0+2 : end-1;
    int b3 = (b0+3 < end) ? b0+3 : end-1;
    float* wsm = sV + warp * 4 * Un;       // 512 floats per warp

    // sensory accumulators (f32x2 pairs: (b0,b1) and (b2,b3))
    u64 n01[4], d01[4], n23[4], d23[4];
    #pragma unroll
    for (int j = 0; j < 4; ++j) { n01[j]=0; d01[j]=0; n23[j]=0; d23[j]=0; }

    // ---- B: sensory tanh sums for 4 batches ----
    if (lane < 16) {
        int s4i = lane * 4;
        float4 iw = *(const float4*)(inw + s4i);
        float4 ib = *(const float4*)(inb + s4i);
        const int bs[4] = {b0, b1, b2, b3};
        #pragma unroll
        for (int q = 0; q < 4; ++q) {
            float4 x = *(const float4*)(inputs + bs[q]*Sn + s4i);
            float4 r;
            r.x = fmaf(x.x, iw.x, ib.x); r.y = fmaf(x.y, iw.y, ib.y);
            r.z = fmaf(x.z, iw.z, ib.z); r.w = fmaf(x.w, iw.w, ib.w);
            ((float4*)(wsm + q*64))[lane] = r;
        }
    }
    __syncwarp();
    {
        const float4* A4 = (const float4*)sAf;
        const float4* B4 = (const float4*)sBf;
        const float4* W4 = (const float4*)sWf;
        #pragma unroll 2
        for (int s = 0; s < Sn; ++s) {
            float x0 = wsm[s], x1 = wsm[64+s], x2 = wsm[128+s], x3 = wsm[192+s];
            float4 a  = A4[s*32 + lane];
            float4 bb = B4[s*32 + lane];
            float4 we = W4[s*32 + lane];
            const float av[4] = {a.x, a.y, a.z, a.w};
            const float bv[4] = {bb.x, bb.y, bb.z, bb.w};
            const float wv[4] = {we.x, we.y, we.z, we.w};
            #pragma unroll
            for (int j = 0; j < 4; ++j) {
                u64 wsp  = pk2(wv[j], wv[j]);
                u64 wasp = wsp & 0x7FFFFFFF7FFFFFFFULL;
                float t0 = ftanh(fmaf(av[j], x0, bv[j]));
                float t1 = ftanh(fmaf(av[j], x1, bv[j]));
                float t2 = ftanh(fmaf(av[j], x2, bv[j]));
                float t3 = ftanh(fmaf(av[j], x3, bv[j]));
                u64 p01 = pk2(t0, t1), p23 = pk2(t2, t3);
                n01[j] = fma2(p01, wsp, n01[j]); d01[j] = fma2(p01, wasp, d01[j]);
                n23[j] = fma2(p23, wsp, n23[j]); d23[j] = fma2(p23, wasp, d23[j]);
            }
        }
    }
    // sensory column sums (threads 0..127)
    if (tid < Un) {
        float n = 0.f, d = 0.f;
        #pragma unroll 8
        for (int s = 0; s < Sn; ++s) {
            float wv = sWf[s*Un + tid];
            n += wv; d += fabsf(wv);
        }
        sSCn[tid] = n; sSCd[tid] = d;
    }
    __syncthreads();

    // ---- A2: fold recurrent params into SMEM (overwrite) ----
    {
        const float4* s4 = (const float4*)sigma;
        const float4* m4 = (const float4*)mu;
        const float4* w4 = (const float4*)w;
        const float4* e4 = (const float4*)erev;
        const float4* k4 = (const float4*)mask;
        for (int i = tid; i < Un*Un/4; i += NTHR) {
            float4 sg = s4[i], mm = m4[i], ww = w4[i], ee = e4[i], kk = k4[i];
            float4 a, b, we;
            a.x = 0.5f*sg.x; a.y = 0.5f*sg.y; a.z = 0.5f*sg.z; a.w = 0.5f*sg.w;
            b.x = -a.x*mm.x; b.y = -a.y*mm.y; b.z = -a.z*mm.z; b.w = -a.w*mm.w;
            we.x = 0.5f*ww.x*kk.x*ee.x; we.y = 0.5f*ww.y*kk.y*ee.y;
            we.z = 0.5f*ww.z*kk.z*ee.z; we.w = 0.5f*ww.w*kk.w*ee.w;
            ((float4*)sAf)[i] = a; ((float4*)sBf)[i] = b; ((float4*)sWf)[i] = we;
        }
    }
    __syncthreads();

    // ---- B2: assemble nbase/dbase ----
    if (tid < Un) {
        float n = sSCn[tid], d = sSCd[tid];
        #pragma unroll 8
        for (int s = 0; s < Un; ++s) {
            float wv = sWf[s*Un + tid];
            n += wv; d += fabsf(wv);
        }
        float gl = gleak[tid];
        sNB[tid] = fmaf(gl, vleak[tid], n);
        sDB[tid] = cm[tid]*(float)NUNF + gl + EPSF + d;
    }
    __syncthreads();

    // ---- per-dst init constants ----
    float4 cmt;
    u64 in01[4], id01[4], in23[4], id23[4];
    {
        float4 cm4 = *(const float4*)(cm  + d0);
        float4 nb4 = *(const float4*)(sNB + d0);
        float4 db4 = *(const float4*)(sDB + d0);
        cmt.x = cm4.x*(float)NUNF; cmt.y = cm4.y*(float)NUNF;
        cmt.z = cm4.z*(float)NUNF; cmt.w = cm4.w*(float)NUNF;
        const float nbv[4] = {nb4.x, nb4.y, nb4.z, nb4.w};
        const float dbv[4] = {db4.x, db4.y, db4.z, db4.w};
        #pragma unroll
        for (int j = 0; j < 4; ++j) {
            in01[j] = pk2(nbv[j] + lo2(n01[j]), nbv[j] + hi2(n01[j]));
            id01[j] = pk2(dbv[j] + lo2(d01[j]), dbv[j] + hi2(d01[j]));
            in23[j] = pk2(nbv[j] + lo2(n23[j]), nbv[j] + hi2(n23[j]));
            id23[j] = pk2(dbv[j] + lo2(d23[j]), dbv[j] + hi2(d23[j]));
        }
    }

    const float4* sA = (const float4*)sAf;
    const float4* sB = (const float4*)sBf;
    const float4* sW = (const float4*)sWf;

    // v state: wsm[0..255] = (v_b0,v_b1) pairs; wsm[256..511] = (v_b2,v_b3)
    float4 v0 = *(const float4*)(state + b0*Un + d0);
    float4 v1 = *(const float4*)(state + b1*Un + d0);
    float4 v2 = *(const float4*)(state + b2*Un + d0);
    float4 v3 = *(const float4*)(state + b3*Un + d0);
    float2* vp01 = (float2*)wsm;
    float2* vp23 = (float2*)(wsm + 2*Un);
    vp01[d0+0] = make_float2(v0.x, v1.x); vp23[d0+0] = make_float2(v2.x, v3.x);
    vp01[d0+1] = make_float2(v0.y, v1.y); vp23[d0+1] = make_float2(v2.y, v3.y);
    vp01[d0+2] = make_float2(v0.z, v1.z); vp23[d0+2] = make_float2(v2.z, v3.z);
    vp01[d0+3] = make_float2(v0.w, v1.w); vp23[d0+3] = make_float2(v2.w, v3.w);
    __syncwarp();

    for (int it = 0; it < NUNF; ++it) {
        u64 m01[4], e01[4], m23[4], e23[4];
        #pragma unroll
        for (int j = 0; j < 4; ++j) { m01[j]=in01[j]; e01[j]=id01[j]; m23[j]=in23[j]; e23[j]=id23[j]; }

        #pragma unroll 2
        for (int s = 0; s < Un; ++s) {
            float2 vs01 = vp01[s];
            float2 vs23 = vp23[s];
            float4 a  = sA[s*32 + lane];
            float4 bb = sB[s*32 + lane];
            float4 we = sW[s*32 + lane];
            const float av[4] = {a.x, a.y, a.z, a.w};
            const float bv[4] = {bb.x, bb.y, bb.z, bb.w};
            const float wv[4] = {we.x, we.y, we.z, we.w};
            #pragma unroll
            for (int j = 0; j < 4; ++j) {
                u64 wsp  = pk2(wv[j], wv[j]);
                u64 wasp = wsp & 0x7FFFFFFF7FFFFFFFULL;
                float t0 = ftanh(fmaf(av[j], vs01.x, bv[j]));
                float t1 = ftanh(fmaf(av[j], vs01.y, bv[j]));
                float t2 = ftanh(fmaf(av[j], vs23.x, bv[j]));
                float t3 = ftanh(fmaf(av[j], vs23.y, bv[j]));
                u64 p01 = pk2(t0, t1), p23 = pk2(t2, t3);
                m01[j] = fma2(p01, wsp, m01[j]); e01[j] = fma2(p01, wasp, e01[j]);
                m23[j] = fma2(p23, wsp, m23[j]); e23[j] = fma2(p23, wasp, e23[j]);
            }
        }

        float vn0[4], vn1[4], vn2[4], vn3[4];
        const float cmv[4] = {cmt.x, cmt.y, cmt.z, cmt.w};
        const float v0v[4] = {v0.x, v0.y, v0.z, v0.w};
        const float v1v[4] = {v1.x, v1.y, v1.z, v1.w};
        const float v2v[4] = {v2.x, v2.y, v2.z, v2.w};
        const float v3v[4] = {v3.x, v3.y, v3.z, v3.w};
        #pragma unroll
        for (int j = 0; j < 4; ++j) {
            vn0[j] = __fdividef(fmaf(cmv[j], v0v[j], lo2(m01[j])), lo2(e01[j]));
            vn1[j] = __fdividef(fmaf(cmv[j], v1v[j], hi2(m01[j])), hi2(e01[j]));
            vn2[j] = __fdividef(fmaf(cmv[j], v2v[j], lo2(m23[j])), lo2(e23[j]));
            vn3[j] = __fdividef(fmaf(cmv[j], v3v[j], hi2(m23[j])), hi2(e23[j]));
        }
        __syncwarp();
        #pragma unroll
        for (int j = 0; j < 4; ++j) {
            vp01[d0+j] = make_float2(vn0[j], vn1[j]);
            vp23[d0+j] = make_float2(vn2[j], vn3[j]);
        }
        __syncwarp();
        v0 = make_float4(vn0[0], vn0[1], vn0[2], vn0[3]);
        v1 = make_float4(vn1[0], vn1[1], vn1[2], vn1[3]);
        v2 = make_float4(vn2[0], vn2[1], vn2[2], vn2[3]);
        v3 = make_float4(vn3[0], vn3[1], vn3[2], vn3[3]);
    }

    // outputs: v section [B*M, B*M+B*U), motor [0, B*M)
    ((float4*)(dout + Bn*Mn + b0*Un))[lane] = v0;
    ((float4*)(dout + Bn*Mn + b1*Un))[lane] = v1;
    ((float4*)(dout + Bn*Mn + b2*Un))[lane] = v2;
    ((float4*)(dout + Bn*Mn + b3*Un))[lane] = v3;
    if (d0 < Mn) {
        float4 ow = *(const float4*)(outw + d0);
        float4 ob = *(const float4*)(outb + d0);
        float4 o;
        o.x = fmaf(v0.x, ow.x, ob.x); o.y = fmaf(v0.y, ow.y, ob.y);
        o.z = fmaf(v0.z, ow.z, ob.z); o.w = fmaf(v0.w, ow.w, ob.w);
        ((float4*)(dout + b0*Mn))[lane] = o;
        o.x = fmaf(v1.x, ow.x, ob.x); o.y = fmaf(v1.y, ow.y, ob.y);
        o.z = fmaf(v1.z, ow.z, ob.z); o.w = fmaf(v1.w, ow.w, ob.w);
        ((float4*)(dout + b1*Mn))[lane] = o;
        o.x = fmaf(v2.x, ow.x, ob.x); o.y = fmaf(v2.y, ow.y, ob.y);
        o.z = fmaf(v2.z, ow.z, ob.z); o.w = fmaf(v2.w, ow.w, ob.w);
        ((float4*)(dout + b2*Mn))[lane] = o;
        o.x = fmaf(v3.x, ow.x, ob.x); o.y = fmaf(v3.y, ow.y, ob.y);
        o.z = fmaf(v3.z, ow.z, ob.z); o.w = fmaf(v3.w, ow.w, ob.w);
        ((float4*)(dout + b3*Mn))[lane] = o;
    }
}

extern "C" void kernel_launch(void* const* d_in, const int* in_sizes, int n_in,
                              void* d_out, int out_size) {
    const float* inputs = (const float*)d_in[0];
    const float* state  = (const float*)d_in[1];
    const float* gleak  = (const float*)d_in[2];
    const float* vleak  = (const float*)d_in[3];
    const float* cm     = (const float*)d_in[4];
    const float* sigma  = (const float*)d_in[5];
    const float* mu     = (const float*)d_in[6];
    const float* w      = (const float*)d_in[7];
    const float* erev   = (const float*)d_in[8];
    const float* ssig   = (const float*)d_in[9];
    const float* smu    = (const float*)d_in[10];
    const float* sw     = (const float*)d_in[11];
    const float* serev  = (const float*)d_in[12];
    const float* mask   = (const float*)d_in[13];
    const float* smask  = (const float*)d_in[14];
    const float* inw    = (const float*)d_in[15];
    const float* inb    = (const float*)d_in[16];
    const float* outw   = (const float*)d_in[17];
    const float* outb   = (const float*)d_in[18];
    float* out = (float*)d_out;

    size_t shmem = (size_t)(3*Un*Un + NWARP*4*Un + 4*Un) * sizeof(float);  // ~208 KB
    cudaFuncSetAttribute(ltc_all, cudaFuncAttributeMaxDynamicSharedMemorySize, (int)shmem);
    ltc_all<<<148, NTHR, shmem>>>(inputs, state, gleak, vleak, cm,
                                  sigma, mu, w, erev, ssig, smu, sw, serev,
                                  mask, smask, inw, inb, outw, outb, out);
}

// round 7
// speedup vs baseline: 1.0733x; 1.0733x over previous
#include <cuda_runtime.h>

#define Bn 4096
#define Sn 64
#define Un 128
#define Mn 32
#define NUNF 6
#define EPSF 1e-8f
#define NPAIR 7
#define NWARP (2*NPAIR)
#define NTHR (NWARP*32)

__device__ __forceinline__ float ftanh(float x) {
    float t; asm("tanh.approx.f32 %0, %1;" : "=f"(t) : "f"(x));
    return t;
}
__device__ __forceinline__ void barpair(int pid) {
    asm volatile("bar.sync %0, 64;" :: "r"(pid + 1) : "memory");
}

// Single fused kernel. 148 CTAs x 448 threads (14 warps).
// Warp pair (p, p+7) shares 4 batch elements: LOW warp p owns src s in [0,64),
// HIGH warp p+7 owns s in [64,128). Partial num/den sums exchanged via SMEM
// each unfold. lane owns dst 4*lane..4*lane+3.
__global__ __launch_bounds__(NTHR, 1) void ltc_all(
    const float* __restrict__ inputs, const float* __restrict__ state,
    const float* __restrict__ gleak,  const float* __restrict__ vleak,
    const float* __restrict__ cm,
    const float* __restrict__ sigma,  const float* __restrict__ mu,
    const float* __restrict__ w,      const float* __restrict__ erev,
    const float* __restrict__ ssig,   const float* __restrict__ smu,
    const float* __restrict__ sw,     const float* __restrict__ serev,
    const float* __restrict__ mask,   const float* __restrict__ smask,
    const float* __restrict__ inw,    const float* __restrict__ inb,
    const float* __restrict__ outw,   const float* __restrict__ outb,
    float* __restrict__ dout)
{
    extern __shared__ float sm[];
    float* sAf = sm;                         // Un*Un  a = 0.5*sigma
    float* sBf = sm + Un*Un;                 // Un*Un  b = -0.5*sigma*mu
    float* sWf = sm + 2*Un*Un;               // Un*Un  we = 0.5*w*mask*erev
    float* sVp = sm + 3*Un*Un;               // NPAIR*512: v pairs per pair
    float* sXc = sVp + NPAIR*512;            // NPAIR*512: exchange / x staging
    float* sSCn = sXc + NPAIR*512;           // Un sensory col num-sums
    float* sSCd = sSCn + Un;
    float* sNB  = sSCd + Un;                 // Un nbase
    float* sDB  = sNB + Un;                  // Un dbase

    int tid = threadIdx.x;

    // ---- A1: fold sensory params into SMEM ----
    {
        const float4* s4 = (const float4*)ssig;
        const float4* m4 = (const float4*)smu;
        const float4* w4 = (const float4*)sw;
        const float4* e4 = (const float4*)serev;
        const float4* k4 = (const float4*)smask;
        for (int i = tid; i < Sn*Un/4; i += NTHR) {
            float4 sg = s4[i], mm = m4[i], ww = w4[i], ee = e4[i], kk = k4[i];
            float4 a, b, we;
            a.x = 0.5f*sg.x; a.y = 0.5f*sg.y; a.z = 0.5f*sg.z; a.w = 0.5f*sg.w;
            b.x = -a.x*mm.x; b.y = -a.y*mm.y; b.z = -a.z*mm.z; b.w = -a.w*mm.w;
            we.x = 0.5f*ww.x*kk.x*ee.x; we.y = 0.5f*ww.y*kk.y*ee.y;
            we.z = 0.5f*ww.z*kk.z*ee.z; we.w = 0.5f*ww.w*kk.w*ee.w;
            ((float4*)sAf)[i] = a; ((float4*)sBf)[i] = b; ((float4*)sWf)[i] = we;
        }
    }
    __syncthreads();

    int warp = tid >> 5, lane = tid & 31, d0 = lane * 4;
    int pid = warp % NPAIR;
    bool hi = (warp >= NPAIR);
    int start = (int)(((long long)blockIdx.x       * Bn) / gridDim.x);
    int end   = (int)(((long long)(blockIdx.x + 1) * Bn) / gridDim.x);
    int b0 = start + pid*4;
    int b1 = (b0+1 < end) ? b0+1 : end-1;
    int b2 = (b0+2 < end) ? b0+2 : end-1;
    int b3 = (b0+3 < end) ? b0+3 : end-1;
    float* vp01 = sVp + pid*512;             // 128 float2 (v_b0, v_b1)
    float* vp23 = vp01 + 256;                // 128 float2 (v_b2, v_b3)
    float* xch  = sXc + pid*512;             // 512-float exchange buffer

    // ---- stage x rows (LOW warp) ----
    if (!hi && lane < 16) {
        int s4i = lane * 4;
        float4 iw = *(const float4*)(inw + s4i);
        float4 ib = *(const float4*)(inb + s4i);
        const int bs[4] = {b0, b1, b2, b3};
        #pragma unroll
        for (int q = 0; q < 4; ++q) {
            float4 x = *(const float4*)(inputs + bs[q]*Sn + s4i);
            float4 r;
            r.x = fmaf(x.x, iw.x, ib.x); r.y = fmaf(x.y, iw.y, ib.y);
            r.z = fmaf(x.z, iw.z, ib.z); r.w = fmaf(x.w, iw.w, ib.w);
            ((float4*)(xch + q*64))[lane] = r;
        }
    }
    barpair(pid);

    // ---- sensory partial sums: LOW s in [0,32), HIGH s in [32,64) ----
    float4 aN0 = make_float4(0,0,0,0), aN1 = aN0, aN2 = aN0, aN3 = aN0;
    float4 aD0 = aN0, aD1 = aN0, aD2 = aN0, aD3 = aN0;
    {
        const float4* A4 = (const float4*)sAf;
        const float4* B4 = (const float4*)sBf;
        const float4* W4 = (const float4*)sWf;
        int ss0 = hi ? 32 : 0;
        #pragma unroll 2
        for (int s = ss0; s < ss0 + 32; ++s) {
            float x0 = xch[s], x1 = xch[64+s], x2 = xch[128+s], x3 = xch[192+s];
            float4 a  = A4[s*32 + lane];
            float4 bb = B4[s*32 + lane];
            float4 we = W4[s*32 + lane];
            #define SSTEP(AJ,BJ,WJ,F) { \
                float wa = fabsf(WJ); float t; \
                t = ftanh(fmaf(AJ, x0, BJ)); aN0.F = fmaf(t,WJ,aN0.F); aD0.F = fmaf(t,wa,aD0.F); \
                t = ftanh(fmaf(AJ, x1, BJ)); aN1.F = fmaf(t,WJ,aN1.F); aD1.F = fmaf(t,wa,aD1.F); \
                t = ftanh(fmaf(AJ, x2, BJ)); aN2.F = fmaf(t,WJ,aN2.F); aD2.F = fmaf(t,wa,aD2.F); \
                t = ftanh(fmaf(AJ, x3, BJ)); aN3.F = fmaf(t,WJ,aN3.F); aD3.F = fmaf(t,wa,aD3.F); }
            SSTEP(a.x, bb.x, we.x, x)
            SSTEP(a.y, bb.y, we.y, y)
            SSTEP(a.z, bb.z, we.z, z)
            SSTEP(a.w, bb.w, we.w, w)
            #undef SSTEP
        }
    }
    // sensory column sums (threads 0..127)
    if (tid < Un) {
        float n = 0.f, d = 0.f;
        #pragma unroll 8
        for (int s = 0; s < Sn; ++s) {
            float wv = sWf[s*Un + tid];
            n += wv; d += fabsf(wv);
        }
        sSCn[tid] = n; sSCd[tid] = d;
    }
    __syncthreads();

    // ---- A2: fold recurrent params into SMEM (overwrite) ----
    {
        const float4* s4 = (const float4*)sigma;
        const float4* m4 = (const float4*)mu;
        const float4* w4 = (const float4*)w;
        const float4* e4 = (const float4*)erev;
        const float4* k4 = (const float4*)mask;
        for (int i = tid; i < Un*Un/4; i += NTHR) {
            float4 sg = s4[i], mm = m4[i], ww = w4[i], ee = e4[i], kk = k4[i];
            float4 a, b, we;
            a.x = 0.5f*sg.x; a.y = 0.5f*sg.y; a.z = 0.5f*sg.z; a.w = 0.5f*sg.w;
            b.x = -a.x*mm.x; b.y = -a.y*mm.y; b.z = -a.z*mm.z; b.w = -a.w*mm.w;
            we.x = 0.5f*ww.x*kk.x*ee.x; we.y = 0.5f*ww.y*kk.y*ee.y;
            we.z = 0.5f*ww.z*kk.z*ee.z; we.w = 0.5f*ww.w*kk.w*ee.w;
            ((float4*)sAf)[i] = a; ((float4*)sBf)[i] = b; ((float4*)sWf)[i] = we;
        }
    }
    __syncthreads();

    // ---- B2: assemble nbase/dbase ----
    if (tid < Un) {
        float n = sSCn[tid], d = sSCd[tid];
        #pragma unroll 8
        for (int s = 0; s < Un; ++s) {
            float wv = sWf[s*Un + tid];
            n += wv; d += fabsf(wv);
        }
        float gl = gleak[tid];
        sNB[tid] = fmaf(gl, vleak[tid], n);
        sDB[tid] = cm[tid]*(float)NUNF + gl + EPSF + d;
    }
    __syncthreads();

    // ---- init constants; bases folded only into LOW warp's partials ----
    float4 cmt;
    {
        float4 cm4 = *(const float4*)(cm + d0);
        cmt.x = cm4.x*(float)NUNF; cmt.y = cm4.y*(float)NUNF;
        cmt.z = cm4.z*(float)NUNF; cmt.w = cm4.w*(float)NUNF;
        if (!hi) {
            float4 nb4 = *(const float4*)(sNB + d0);
            float4 db4 = *(const float4*)(sDB + d0);
            #define ADD4(T,S) T.x += S.x; T.y += S.y; T.z += S.z; T.w += S.w;
            ADD4(aN0, nb4) ADD4(aN1, nb4) ADD4(aN2, nb4) ADD4(aN3, nb4)
            ADD4(aD0, db4) ADD4(aD1, db4) ADD4(aD2, db4) ADD4(aD3, db4)
            #undef ADD4
        }
    }

    const float4* sA = (const float4*)sAf;
    const float4* sB = (const float4*)sBf;
    const float4* sW = (const float4*)sWf;

    // v init: LOW keeps (b0,b1) in regs + writes vp01; HIGH keeps (b2,b3) + vp23.
    float4 vA, vB;
    {
        int ba = hi ? b2 : b0, bb = hi ? b3 : b1;
        vA = *(const float4*)(state + ba*Un + d0);
        vB = *(const float4*)(state + bb*Un + d0);
        float2* vw = (float2*)(hi ? vp23 : vp01);
        vw[d0+0] = make_float2(vA.x, vB.x);
        vw[d0+1] = make_float2(vA.y, vB.y);
        vw[d0+2] = make_float2(vA.z, vB.z);
        vw[d0+3] = make_float2(vA.w, vB.w);
    }
    barpair(pid);

    const int sLo = hi ? 64 : 0;
    float4* x4 = (float4*)xch;

    for (int it = 0; it < NUNF; ++it) {
        float4 mN0 = aN0, mN1 = aN1, mN2 = aN2, mN3 = aN3;
        float4 mD0 = aD0, mD1 = aD1, mD2 = aD2, mD3 = aD3;

        #pragma unroll 4
        for (int s = sLo; s < sLo + 64; ++s) {
            float2 vs01 = ((const float2*)vp01)[s];
            float2 vs23 = ((const float2*)vp23)[s];
            float4 a  = sA[s*32 + lane];
            float4 bb = sB[s*32 + lane];
            float4 we = sW[s*32 + lane];
            #define RSTEP(AJ,BJ,WJ,F) { \
                float wa = fabsf(WJ); float t; \
                t = ftanh(fmaf(AJ, vs01.x, BJ)); mN0.F = fmaf(t,WJ,mN0.F); mD0.F = fmaf(t,wa,mD0.F); \
                t = ftanh(fmaf(AJ, vs01.y, BJ)); mN1.F = fmaf(t,WJ,mN1.F); mD1.F = fmaf(t,wa,mD1.F); \
                t = ftanh(fmaf(AJ, vs23.x, BJ)); mN2.F = fmaf(t,WJ,mN2.F); mD2.F = fmaf(t,wa,mD2.F); \
                t = ftanh(fmaf(AJ, vs23.y, BJ)); mN3.F = fmaf(t,WJ,mN3.F); mD3.F = fmaf(t,wa,mD3.F); }
            RSTEP(a.x, bb.x, we.x, x)
            RSTEP(a.y, bb.y, we.y, y)
            RSTEP(a.z, bb.z, we.z, z)
            RSTEP(a.w, bb.w, we.w, w)
            #undef RSTEP
        }

        // ---- pairwise exchange & update ----
        float4 vnA, vnB;
        if (hi) {   // HIGH ships (b0,b1) partials to LOW
            x4[lane]      = mN0;  x4[32 + lane] = mD0;
            x4[64 + lane] = mN1;  x4[96 + lane] = mD1;
        }
        barpair(pid);
        if (!hi) {  // LOW combines (b0,b1), ships (b2,b3)
            float4 pn0 = x4[lane],      pd0 = x4[32 + lane];
            float4 pn1 = x4[64 + lane], pd1 = x4[96 + lane];
            vnA.x = __fdividef(fmaf(cmt.x, vA.x, mN0.x + pn0.x), mD0.x + pd0.x);
            vnA.y = __fdividef(fmaf(cmt.y, vA.y, mN0.y + pn0.y), mD0.y + pd0.y);
            vnA.z = __fdividef(fmaf(cmt.z, vA.z, mN0.z + pn0.z), mD0.z + pd0.z);
            vnA.w = __fdividef(fmaf(cmt.w, vA.w, mN0.w + pn0.w), mD0.w + pd0.w);
            vnB.x = __fdividef(fmaf(cmt.x, vB.x, mN1.x + pn1.x), mD1.x + pd1.x);
            vnB.y = __fdividef(fmaf(cmt.y, vB.y, mN1.y + pn1.y), mD1.y + pd1.y);
            vnB.z = __fdividef(fmaf(cmt.z, vB.z, mN1.z + pn1.z), mD1.z + pd1.z);
            vnB.w = __fdividef(fmaf(cmt.w, vB.w, mN1.w + pn1.w), mD1.w + pd1.w);
            x4[lane]      = mN2;  x4[32 + lane] = mD2;
            x4[64 + lane] = mN3;  x4[96 + lane] = mD3;
        }
        barpair(pid);
        if (hi) {   // HIGH combines (b2,b3)
            float4 pn2 = x4[lane],      pd2 = x4[32 + lane];
            float4 pn3 = x4[64 + lane], pd3 = x4[96 + lane];
            vnA.x = __fdividef(fmaf(cmt.x, vA.x, mN2.x + pn2.x), mD2.x + pd2.x);
            vnA.y = __fdividef(fmaf(cmt.y, vA.y, mN2.y + pn2.y), mD2.y + pd2.y);
            vnA.z = __fdividef(fmaf(cmt.z, vA.z, mN2.z + pn2.z), mD2.z + pd2.z);
            vnA.w = __fdividef(fmaf(cmt.w, vA.w, mN2.w + pn2.w), mD2.w + pd2.w);
            vnB.x = __fdividef(fmaf(cmt.x, vB.x, mN3.x + pn3.x), mD3.x + pd3.x);
            vnB.y = __fdividef(fmaf(cmt.y, vB.y, mN3.y + pn3.y), mD3.y + pd3.y);
            vnB.z = __fdividef(fmaf(cmt.z, vB.z, mN3.z + pn3.z), mD3.z + pd3.z);
            vnB.w = __fdividef(fmaf(cmt.w, vB.w, mN3.w + pn3.w), mD3.w + pd3.w);
        }
        // publish new v pairs
        {
            float2* vw = (float2*)(hi ? vp23 : vp01);
            vw[d0+0] = make_float2(vnA.x, vnB.x);
            vw[d0+1] = make_float2(vnA.y, vnB.y);
            vw[d0+2] = make_float2(vnA.z, vnB.z);
            vw[d0+3] = make_float2(vnA.w, vnB.w);
        }
        vA = vnA; vB = vnB;
        barpair(pid);
    }

    // ---- outputs: each warp writes its 2 finalized batches ----
    int ba = hi ? b2 : b0, bb = hi ? b3 : b1;
    ((float4*)(dout + Bn*Mn + ba*Un))[lane] = vA;
    ((float4*)(dout + Bn*Mn + bb*Un))[lane] = vB;
    if (d0 < Mn) {
        float4 ow = *(const float4*)(outw + d0);
        float4 ob = *(const float4*)(outb + d0);
        float4 o;
        o.x = fmaf(vA.x, ow.x, ob.x); o.y = fmaf(vA.y, ow.y, ob.y);
        o.z = fmaf(vA.z, ow.z, ob.z); o.w = fmaf(vA.w, ow.w, ob.w);
        ((float4*)(dout + ba*Mn))[lane] = o;
        o.x = fmaf(vB.x, ow.x, ob.x); o.y = fmaf(vB.y, ow.y, ob.y);
        o.z = fmaf(vB.z, ow.z, ob.z); o.w = fmaf(vB.w, ow.w, ob.w);
        ((float4*)(dout + bb*Mn))[lane] = o;
    }
}

extern "C" void kernel_launch(void* const* d_in, const int* in_sizes, int n_in,
                              void* d_out, int out_size) {
    const float* inputs = (const float*)d_in[0];
    const float* state  = (const float*)d_in[1];
    const float* gleak  = (const float*)d_in[2];
    const float* vleak  = (const float*)d_in[3];
    const float* cm     = (const float*)d_in[4];
    const float* sigma  = (const float*)d_in[5];
    const float* mu     = (const float*)d_in[6];
    const float* w      = (const float*)d_in[7];
    const float* erev   = (const float*)d_in[8];
    const float* ssig   = (const float*)d_in[9];
    const float* smu    = (const float*)d_in[10];
    const float* sw     = (const float*)d_in[11];
    const float* serev  = (const float*)d_in[12];
    const float* mask   = (const float*)d_in[13];
    const float* smask  = (const float*)d_in[14];
    const float* inw    = (const float*)d_in[15];
    const float* inb    = (const float*)d_in[16];
    const float* outw   = (const float*)d_in[17];
    const float* outb   = (const float*)d_in[18];
    float* out = (float*)d_out;

    size_t shmem = (size_t)(3*Un*Un + NPAIR*512*2 + 4*Un) * sizeof(float);  // 227.3 KB
    cudaFuncSetAttribute(ltc_all, cudaFuncAttributeMaxDynamicSharedMemorySize, (int)shmem);
    ltc_all<<<148, NTHR, shmem>>>(inputs, state, gleak, vleak, cm,
                                  sigma, mu, w, erev, ssig, smu, sw, serev,
                                  mask, smask, inw, inb, outw, outb, out);
}

// round 8
// speedup vs baseline: 1.2613x; 1.1751x over previous
#include <cuda_runtime.h>

#define Bn 4096
#define Sn 64
#define Un 128
#define Mn 32
#define NUNF 6
#define EPSF 1e-8f
#define NPAIR 7
#define NWARP (2*NPAIR)
#define NTHR (NWARP*32)

__device__ __forceinline__ float ftanh(float x) {
    float t; asm("tanh.approx.f32 %0, %1;" : "=f"(t) : "f"(x));
    return t;
}
__device__ __forceinline__ void barpair(int pid) {
    asm volatile("bar.sync %0, 64;" :: "r"(pid + 1) : "memory");
}

// Fused LTC kernel, sparsity-compacted recurrent loop.
// 148 CTAs x 448 threads (14 warps = 7 pairs). Pair (p, p+7) shares 4 batches.
// Recurrent weights are compacted per-dst (50% mask) with the src index embedded
// in the low 7 mantissa bits of 'a'; v is gathered as float4 (4 batches) per src.
__global__ __launch_bounds__(NTHR, 1) void ltc_all(
    const float* __restrict__ inputs, const float* __restrict__ state,
    const float* __restrict__ gleak,  const float* __restrict__ vleak,
    const float* __restrict__ cm,
    const float* __restrict__ sigma,  const float* __restrict__ mu,
    const float* __restrict__ w,      const float* __restrict__ erev,
    const float* __restrict__ ssig,   const float* __restrict__ smu,
    const float* __restrict__ sw,     const float* __restrict__ serev,
    const float* __restrict__ mask,   const float* __restrict__ smask,
    const float* __restrict__ inw,    const float* __restrict__ inb,
    const float* __restrict__ outw,   const float* __restrict__ outb,
    float* __restrict__ dout)
{
    extern __shared__ float sm[];
    float* sAf = sm;                         // Un*Un plane: a (later compacted, idx-embedded)
    float* sBf = sm + Un*Un;                 // Un*Un plane: b
    float* sWf = sm + 2*Un*Un;               // Un*Un plane: we
    float* sVq = sm + 3*Un*Un;               // NPAIR*512: v as float4 (b0,b1,b2,b3) per src
    float* sXc = sVq + NPAIR*512;            // NPAIR*512: exchange / x staging
    float* sSCn = sXc + NPAIR*512;           // Un sensory col num-sums
    float* sSCd = sSCn + Un;
    float* sNB  = sSCd + Un;                 // Un nbase
    float* sDB  = sNB + Un;                  // Un dbase
    int*   sL   = (int*)(sDB + Un);          // max active count

    int tid = threadIdx.x;
    if (tid == 0) *sL = 0;

    // ---- A1: fold sensory params into SMEM (dense) ----
    {
        const float4* s4 = (const float4*)ssig;
        const float4* m4 = (const float4*)smu;
        const float4* w4 = (const float4*)sw;
        const float4* e4 = (const float4*)serev;
        const float4* k4 = (const float4*)smask;
        for (int i = tid; i < Sn*Un/4; i += NTHR) {
            float4 sg = s4[i], mm = m4[i], ww = w4[i], ee = e4[i], kk = k4[i];
            float4 a, b, we;
            a.x = 0.5f*sg.x; a.y = 0.5f*sg.y; a.z = 0.5f*sg.z; a.w = 0.5f*sg.w;
            b.x = -a.x*mm.x; b.y = -a.y*mm.y; b.z = -a.z*mm.z; b.w = -a.w*mm.w;
            we.x = 0.5f*ww.x*kk.x*ee.x; we.y = 0.5f*ww.y*kk.y*ee.y;
            we.z = 0.5f*ww.z*kk.z*ee.z; we.w = 0.5f*ww.w*kk.w*ee.w;
            ((float4*)sAf)[i] = a; ((float4*)sBf)[i] = b; ((float4*)sWf)[i] = we;
        }
    }
    __syncthreads();

    int warp = tid >> 5, lane = tid & 31, d0 = lane * 4;
    int pid = warp % NPAIR;
    bool hi = (warp >= NPAIR);
    int start = (int)(((long long)blockIdx.x       * Bn) / gridDim.x);
    int end   = (int)(((long long)(blockIdx.x + 1) * Bn) / gridDim.x);
    int b0 = start + pid*4;
    int b1 = (b0+1 < end) ? b0+1 : end-1;
    int b2 = (b0+2 < end) ? b0+2 : end-1;
    int b3 = (b0+3 < end) ? b0+3 : end-1;
    float* vqp = sVq + pid*512;              // 128 float4 per pair
    float* xch = sXc + pid*512;              // 512-float exchange buffer

    // ---- stage x rows (LOW warp) ----
    if (!hi && lane < 16) {
        int s4i = lane * 4;
        float4 iw = *(const float4*)(inw + s4i);
        float4 ib = *(const float4*)(inb + s4i);
        const int bs[4] = {b0, b1, b2, b3};
        #pragma unroll
        for (int q = 0; q < 4; ++q) {
            float4 x = *(const float4*)(inputs + bs[q]*Sn + s4i);
            float4 r;
            r.x = fmaf(x.x, iw.x, ib.x); r.y = fmaf(x.y, iw.y, ib.y);
            r.z = fmaf(x.z, iw.z, ib.z); r.w = fmaf(x.w, iw.w, ib.w);
            ((float4*)(xch + q*64))[lane] = r;
        }
    }
    barpair(pid);

    // ---- sensory partial sums (dense): LOW s in [0,32), HIGH s in [32,64) ----
    float4 aN0 = make_float4(0,0,0,0), aN1 = aN0, aN2 = aN0, aN3 = aN0;
    float4 aD0 = aN0, aD1 = aN0, aD2 = aN0, aD3 = aN0;
    {
        const float4* A4 = (const float4*)sAf;
        const float4* B4 = (const float4*)sBf;
        const float4* W4 = (const float4*)sWf;
        int ss0 = hi ? 32 : 0;
        #pragma unroll 2
        for (int s = ss0; s < ss0 + 32; ++s) {
            float x0 = xch[s], x1 = xch[64+s], x2 = xch[128+s], x3 = xch[192+s];
            float4 a  = A4[s*32 + lane];
            float4 bb = B4[s*32 + lane];
            float4 we = W4[s*32 + lane];
            #define SSTEP(AJ,BJ,WJ,F) { \
                float wa = fabsf(WJ); float t; \
                t = ftanh(fmaf(AJ, x0, BJ)); aN0.F = fmaf(t,WJ,aN0.F); aD0.F = fmaf(t,wa,aD0.F); \
                t = ftanh(fmaf(AJ, x1, BJ)); aN1.F = fmaf(t,WJ,aN1.F); aD1.F = fmaf(t,wa,aD1.F); \
                t = ftanh(fmaf(AJ, x2, BJ)); aN2.F = fmaf(t,WJ,aN2.F); aD2.F = fmaf(t,wa,aD2.F); \
                t = ftanh(fmaf(AJ, x3, BJ)); aN3.F = fmaf(t,WJ,aN3.F); aD3.F = fmaf(t,wa,aD3.F); }
            SSTEP(a.x, bb.x, we.x, x)
            SSTEP(a.y, bb.y, we.y, y)
            SSTEP(a.z, bb.z, we.z, z)
            SSTEP(a.w, bb.w, we.w, w)
            #undef SSTEP
        }
    }
    if (tid < Un) {   // sensory column sums
        float n = 0.f, d = 0.f;
        #pragma unroll 8
        for (int s = 0; s < Sn; ++s) {
            float wv = sWf[s*Un + tid];
            n += wv; d += fabsf(wv);
        }
        sSCn[tid] = n; sSCd[tid] = d;
    }
    __syncthreads();

    // ---- A2: fold recurrent params into SMEM (dense, overwrite) ----
    {
        const float4* s4 = (const float4*)sigma;
        const float4* m4 = (const float4*)mu;
        const float4* w4 = (const float4*)w;
        const float4* e4 = (const float4*)erev;
        const float4* k4 = (const float4*)mask;
        for (int i = tid; i < Un*Un/4; i += NTHR) {
            float4 sg = s4[i], mm = m4[i], ww = w4[i], ee = e4[i], kk = k4[i];
            float4 a, b, we;
            a.x = 0.5f*sg.x; a.y = 0.5f*sg.y; a.z = 0.5f*sg.z; a.w = 0.5f*sg.w;
            b.x = -a.x*mm.x; b.y = -a.y*mm.y; b.z = -a.z*mm.z; b.w = -a.w*mm.w;
            we.x = 0.5f*ww.x*kk.x*ee.x; we.y = 0.5f*ww.y*kk.y*ee.y;
            we.z = 0.5f*ww.z*kk.z*ee.z; we.w = 0.5f*ww.w*kk.w*ee.w;
            ((float4*)sAf)[i] = a; ((float4*)sBf)[i] = b; ((float4*)sWf)[i] = we;
        }
    }
    __syncthreads();

    // ---- B2: assemble nbase/dbase (dense read) ----
    if (tid < Un) {
        float n = sSCn[tid], d = sSCd[tid];
        #pragma unroll 8
        for (int s = 0; s < Un; ++s) {
            float wv = sWf[s*Un + tid];
            n += wv; d += fabsf(wv);
        }
        float gl = gleak[tid];
        sNB[tid] = fmaf(gl, vleak[tid], n);
        sDB[tid] = cm[tid]*(float)NUNF + gl + EPSF + d;
    }
    __syncthreads();

    // ---- A3: per-dst in-place compaction (thread tid = dst column) ----
    int cnt = 0;
    if (tid < Un) {
        for (int s = 0; s < Un; ++s) {
            float wv = sWf[s*Un + tid];
            if (wv != 0.f) {
                unsigned ai = __float_as_uint(sAf[s*Un + tid]);
                float bv = sBf[s*Un + tid];
                sAf[cnt*Un + tid] = __uint_as_float((ai & 0xFFFFFF80u) | (unsigned)s);
                sBf[cnt*Un + tid] = bv;
                sWf[cnt*Un + tid] = wv;
                cnt++;
            }
        }
        atomicMax(sL, cnt);
    }
    __syncthreads();
    int L = *sL;
    if (tid < Un) {
        for (int e = cnt; e < L; ++e) {   // pad: w=0 -> exact zero contribution
            sAf[e*Un + tid] = 0.f;
            sBf[e*Un + tid] = 0.f;
            sWf[e*Un + tid] = 0.f;
        }
    }
    __syncthreads();

    // ---- init constants; bases folded only into LOW warp's partials ----
    float4 cmt;
    {
        float4 cm4 = *(const float4*)(cm + d0);
        cmt.x = cm4.x*(float)NUNF; cmt.y = cm4.y*(float)NUNF;
        cmt.z = cm4.z*(float)NUNF; cmt.w = cm4.w*(float)NUNF;
        if (!hi) {
            float4 nb4 = *(const float4*)(sNB + d0);
            float4 db4 = *(const float4*)(sDB + d0);
            #define ADD4(T,S) T.x += S.x; T.y += S.y; T.z += S.z; T.w += S.w;
            ADD4(aN0, nb4) ADD4(aN1, nb4) ADD4(aN2, nb4) ADD4(aN3, nb4)
            ADD4(aD0, db4) ADD4(aD1, db4) ADD4(aD2, db4) ADD4(aD3, db4)
            #undef ADD4
        }
    }

    const float4* sA = (const float4*)sAf;
    const float4* sB = (const float4*)sBf;
    const float4* sW = (const float4*)sWf;

    // v init: vq[s] = (v_b0, v_b1, v_b2, v_b3); LOW writes .xy, HIGH writes .zw
    float4 vA, vB;
    {
        int ba = hi ? b2 : b0, bb = hi ? b3 : b1;
        vA = *(const float4*)(state + ba*Un + d0);
        vB = *(const float4*)(state + bb*Un + d0);
        float2* vh = (float2*)vqp;
        int off = hi ? 1 : 0;
        vh[2*(d0+0) + off] = make_float2(vA.x, vB.x);
        vh[2*(d0+1) + off] = make_float2(vA.y, vB.y);
        vh[2*(d0+2) + off] = make_float2(vA.z, vB.z);
        vh[2*(d0+3) + off] = make_float2(vA.w, vB.w);
    }
    barpair(pid);

    int Lh   = (L + 1) >> 1;
    int eBeg = hi ? Lh : 0;
    int eEnd = hi ? L  : Lh;
    float4* x4 = (float4*)xch;
    const float4* vq4 = (const float4*)vqp;

    for (int it = 0; it < NUNF; ++it) {
        float4 mN0 = aN0, mN1 = aN1, mN2 = aN2, mN3 = aN3;
        float4 mD0 = aD0, mD1 = aD1, mD2 = aD2, mD3 = aD3;

        #pragma unroll 2
        for (int e = eBeg; e < eEnd; ++e) {
            float4 a  = sA[e*32 + lane];
            float4 bb = sB[e*32 + lane];
            float4 we = sW[e*32 + lane];
            #define RSTEP(AJ,BJ,WJ,F) { \
                unsigned ai = __float_as_uint(AJ); \
                float af = __uint_as_float(ai & 0xFFFFFF80u); \
                float4 vv = vq4[ai & 0x7Fu]; \
                float wa = fabsf(WJ); float t; \
                t = ftanh(fmaf(af, vv.x, BJ)); mN0.F = fmaf(t,WJ,mN0.F); mD0.F = fmaf(t,wa,mD0.F); \
                t = ftanh(fmaf(af, vv.y, BJ)); mN1.F = fmaf(t,WJ,mN1.F); mD1.F = fmaf(t,wa,mD1.F); \
                t = ftanh(fmaf(af, vv.z, BJ)); mN2.F = fmaf(t,WJ,mN2.F); mD2.F = fmaf(t,wa,mD2.F); \
                t = ftanh(fmaf(af, vv.w, BJ)); mN3.F = fmaf(t,WJ,mN3.F); mD3.F = fmaf(t,wa,mD3.F); }
            RSTEP(a.x, bb.x, we.x, x)
            RSTEP(a.y, bb.y, we.y, y)
            RSTEP(a.z, bb.z, we.z, z)
            RSTEP(a.w, bb.w, we.w, w)
            #undef RSTEP
        }

        // ---- pairwise exchange & update (R7 protocol) ----
        float4 vnA, vnB;
        if (hi) {
            x4[lane]      = mN0;  x4[32 + lane] = mD0;
            x4[64 + lane] = mN1;  x4[96 + lane] = mD1;
        }
        barpair(pid);
        if (!hi) {
            float4 pn0 = x4[lane],      pd0 = x4[32 + lane];
            float4 pn1 = x4[64 + lane], pd1 = x4[96 + lane];
            vnA.x = __fdividef(fmaf(cmt.x, vA.x, mN0.x + pn0.x), mD0.x + pd0.x);
            vnA.y = __fdividef(fmaf(cmt.y, vA.y, mN0.y + pn0.y), mD0.y + pd0.y);
            vnA.z = __fdividef(fmaf(cmt.z, vA.z, mN0.z + pn0.z), mD0.z + pd0.z);
            vnA.w = __fdividef(fmaf(cmt.w, vA.w, mN0.w + pn0.w), mD0.w + pd0.w);
            vnB.x = __fdividef(fmaf(cmt.x, vB.x, mN1.x + pn1.x), mD1.x + pd1.x);
            vnB.y = __fdividef(fmaf(cmt.y, vB.y, mN1.y + pn1.y), mD1.y + pd1.y);
            vnB.z = __fdividef(fmaf(cmt.z, vB.z, mN1.z + pn1.z), mD1.z + pd1.z);
            vnB.w = __fdividef(fmaf(cmt.w, vB.w, mN1.w + pn1.w), mD1.w + pd1.w);
            x4[lane]      = mN2;  x4[32 + lane] = mD2;
            x4[64 + lane] = mN3;  x4[96 + lane] = mD3;
        }
        barpair(pid);
        if (hi) {
            float4 pn2 = x4[lane],      pd2 = x4[32 + lane];
            float4 pn3 = x4[64 + lane], pd3 = x4[96 + lane];
            vnA.x = __fdividef(fmaf(cmt.x, vA.x, mN2.x + pn2.x), mD2.x + pd2.x);
            vnA.y = __fdividef(fmaf(cmt.y, vA.y, mN2.y + pn2.y), mD2.y + pd2.y);
            vnA.z = __fdividef(fmaf(cmt.z, vA.z, mN2.z + pn2.z), mD2.z + pd2.z);
            vnA.w = __fdividef(fmaf(cmt.w, vA.w, mN2.w + pn2.w), mD2.w + pd2.w);
            vnB.x = __fdividef(fmaf(cmt.x, vB.x, mN3.x + pn3.x), mD3.x + pd3.x);
            vnB.y = __fdividef(fmaf(cmt.y, vB.y, mN3.y + pn3.y), mD3.y + pd3.y);
            vnB.z = __fdividef(fmaf(cmt.z, vB.z, mN3.z + pn3.z), mD3.z + pd3.z);
            vnB.w = __fdividef(fmaf(cmt.w, vB.w, mN3.w + pn3.w), mD3.w + pd3.w);
        }
        {   // publish new v halves
            float2* vh = (float2*)vqp;
            int off = hi ? 1 : 0;
            vh[2*(d0+0) + off] = make_float2(vnA.x, vnB.x);
            vh[2*(d0+1) + off] = make_float2(vnA.y, vnB.y);
            vh[2*(d0+2) + off] = make_float2(vnA.z, vnB.z);
            vh[2*(d0+3) + off] = make_float2(vnA.w, vnB.w);
        }
        vA = vnA; vB = vnB;
        barpair(pid);
    }

    // ---- outputs ----
    int ba = hi ? b2 : b0, bb = hi ? b3 : b1;
    ((float4*)(dout + Bn*Mn + ba*Un))[lane] = vA;
    ((float4*)(dout + Bn*Mn + bb*Un))[lane] = vB;
    if (d0 < Mn) {
        float4 ow = *(const float4*)(outw + d0);
        float4 ob = *(const float4*)(outb + d0);
        float4 o;
        o.x = fmaf(vA.x, ow.x, ob.x); o.y = fmaf(vA.y, ow.y, ob.y);
        o.z = fmaf(vA.z, ow.z, ob.z); o.w = fmaf(vA.w, ow.w, ob.w);
        ((float4*)(dout + ba*Mn))[lane] = o;
        o.x = fmaf(vB.x, ow.x, ob.x); o.y = fmaf(vB.y, ow.y, ob.y);
        o.z = fmaf(vB.z, ow.z, ob.z); o.w = fmaf(vB.w, ow.w, ob.w);
        ((float4*)(dout + bb*Mn))[lane] = o;
    }
}

extern "C" void kernel_launch(void* const* d_in, const int* in_sizes, int n_in,
                              void* d_out, int out_size) {
    const float* inputs = (const float*)d_in[0];
    const float* state  = (const float*)d_in[1];
    const float* gleak  = (const float*)d_in[2];
    const float* vleak  = (const float*)d_in[3];
    const float* cm     = (const float*)d_in[4];
    const float* sigma  = (const float*)d_in[5];
    const float* mu     = (const float*)d_in[6];
    const float* w      = (const float*)d_in[7];
    const float* erev   = (const float*)d_in[8];
    const float* ssig   = (const float*)d_in[9];
    const float* smu    = (const float*)d_in[10];
    const float* sw     = (const float*)d_in[11];
    const float* serev  = (const float*)d_in[12];
    const float* mask   = (const float*)d_in[13];
    const float* smask  = (const float*)d_in[14];
    const float* inw    = (const float*)d_in[15];
    const float* inb    = (const float*)d_in[16];
    const float* outw   = (const float*)d_in[17];
    const float* outb   = (const float*)d_in[18];
    float* out = (float*)d_out;

    size_t shmem = (size_t)(3*Un*Un + NPAIR*512*2 + 4*Un + 4) * sizeof(float);  // ~227.3 KB
    cudaFuncSetAttribute(ltc_all, cudaFuncAttributeMaxDynamicSharedMemorySize, (int)shmem);
    ltc_all<<<148, NTHR, shmem>>>(inputs, state, gleak, vleak, cm,
                                  sigma, mu, w, erev, ssig, smu, sw, serev,
                                  mask, smask, inw, inb, outw, outb, out);
}